// round 9
// baseline (speedup 1.0000x reference)
#include <cuda_runtime.h>
#include <cstdint>

// AI4DEM coupling_backward: 3x3 tent-spline gather, 4096x4096 periodic grid.
// Inputs: xp, yp, x_grid(unused), y_grid(unused), vx, vy, Fx, Fy, mask
// Output: 5 planes [alpha, alpha_u, alpha_v, Fx, Fy], each 4096*4096 f32.
//
//   per tap: w = max(0,1-|xp_src - x_dst|) * max(0,1-|yp_src - y_dst|)
//   out     = mask_dst * VP * sum(w * field_src)     (mask at DESTINATION)
//
// R9: double-buffered pipeline with cp.async.bulk (TMA) staging. One elected
// thread issues 60 bulk row-copies per tile against an mbarrier with
// expect_tx; staging consumes no registers and no per-thread issue slots
// (R8's failure: per-thread LDGSTS staging blew regs to 162). Compute body
// is R7's (80 regs). Prefetch of tile i+1 overlaps the full compute of
// tile i, so the DRAM stream is continuous instead of bursty.

#define NXD   4096
#define MASKW 4095

#define BLK_T    128
#define OUT_ROWS 8
#define SRC_ROWS 10                      // OUT_ROWS + 2 halo
#define ROWW     136                     // 4 pad | 128 | 4 pad floats
#define ROW_BYTES (ROWW * 4)             // 544
#define BUF_FLOATS (6 * SRC_ROWS * ROWW) // 8160
#define TILE_BYTES (6 * SRC_ROWS * ROW_BYTES)  // 32640
#define NT       4                       // tiles per block

#define SMF(B, f, r, c) (B)[((f) * SRC_ROWS + (r)) * ROWW + (c)]

__device__ __forceinline__ float tent(float d) {
    return fmaxf(1.0f - fabsf(d), 0.0f);
}
__device__ __forceinline__ constexpr int kmin_of(int s) { return (s - 2 > 0) ? (s - 2) : 0; }
__device__ __forceinline__ constexpr int kmax_of(int s) { return (s < 3) ? s : 3; }

__device__ __forceinline__ void bulk_cp(uint32_t sdst, const float* gsrc,
                                        uint32_t bytes, uint32_t mbar) {
    asm volatile(
        "cp.async.bulk.shared::cta.global.mbarrier::complete_tx::bytes "
        "[%0], [%1], %2, [%3];\n"
        :: "r"(sdst), "l"(gsrc), "r"(bytes), "r"(mbar) : "memory");
}

__device__ __forceinline__ void mbar_wait(uint32_t mbar, uint32_t parity) {
    uint32_t done;
    asm volatile(
        "{\n\t.reg .pred p;\n\t"
        "mbarrier.try_wait.parity.acquire.cta.shared::cta.b64 p, [%1], %2;\n\t"
        "selp.b32 %0, 1, 0, p;\n\t}"
        : "=r"(done) : "r"(mbar), "r"(parity) : "memory");
    if (!done) {
        asm volatile(
            "{\n\t.reg .pred P1;\n\t"
            "WL_%=:\n\t"
            "mbarrier.try_wait.parity.acquire.cta.shared::cta.b64 P1, [%0], %1, 0x989680;\n\t"
            "@P1 bra.uni WD_%=;\n\t"
            "bra.uni WL_%=;\n\t"
            "WD_%=:\n\t}"
            :: "r"(mbar), "r"(parity) : "memory");
    }
}

// Issue all bulk copies for one tile (called by thread 0 only).
__device__ void stage_tile(float* B, uint32_t mbar, int y0b, int gx0,
                           const float* __restrict__ xp, const float* __restrict__ yp,
                           const float* __restrict__ vx, const float* __restrict__ vy,
                           const float* __restrict__ Fx, const float* __restrict__ Fy)
{
    asm volatile("mbarrier.arrive.expect_tx.shared.b64 _, [%0], %1;\n"
                 :: "r"(mbar), "r"((uint32_t)TILE_BYTES) : "memory");

    const bool interior = (gx0 >= 0) && (gx0 + ROWW <= NXD);
    const float* fp[6] = {xp, yp, vx, vy, Fx, Fy};
    #pragma unroll
    for (int f = 0; f < 6; ++f) {
        const float* base = fp[f];
        #pragma unroll
        for (int rr = 0; rr < SRC_ROWS; ++rr) {
            int gy = (y0b - 1 + rr) & MASKW;
            const float* rowp = base + ((size_t)gy << 12);
            uint32_t sdst = (uint32_t)__cvta_generic_to_shared(&SMF(B, f, rr, 0));
            if (interior) {
                bulk_cp(sdst, rowp + gx0, ROW_BYTES, mbar);
            } else if (gx0 < 0) {              // bx==0: left 4 cols wrap
                bulk_cp(sdst,      rowp + (NXD - 4), 16, mbar);
                bulk_cp(sdst + 16, rowp,             ROW_BYTES - 16, mbar);
            } else {                           // bx==31: right 4 cols wrap
                bulk_cp(sdst,                  rowp + gx0, ROW_BYTES - 16, mbar);
                bulk_cp(sdst + ROW_BYTES - 16, rowp,       16, mbar);
            }
        }
    }
}

__global__ void __launch_bounds__(BLK_T, 3)
ai4dem_kernel(const float* __restrict__ xp, const float* __restrict__ yp,
              const float* __restrict__ vx, const float* __restrict__ vy,
              const float* __restrict__ Fx, const float* __restrict__ Fy,
              const float* __restrict__ mk, float* __restrict__ out)
{
    const float VP = 3.1415f / 6.0f;

    extern __shared__ float sdyn[];
    // layout: [0..7] floats = two u64 mbarriers + pad (32B), then two buffers
    float* buf0 = sdyn + 8;
    float* buf1 = buf0 + BUF_FLOATS;
    uint32_t mb0 = (uint32_t)__cvta_generic_to_shared(sdyn);
    uint32_t mb1 = mb0 + 8;

    const int t   = threadIdx.x;
    const int bx  = blockIdx.x & 31;
    const int yg  = blockIdx.x >> 5;
    const int xb0 = bx << 7;
    const int gx0 = xb0 - 4;                  // staged window start col

    if (t == 0) {
        asm volatile("mbarrier.init.shared.b64 [%0], 1;" :: "r"(mb0) : "memory");
        asm volatile("mbarrier.init.shared.b64 [%0], 1;" :: "r"(mb1) : "memory");
        asm volatile("fence.proxy.async.shared::cta;" ::: "memory");
    }
    __syncthreads();

    if (t == 0)
        stage_tile(buf0, mb0, yg * (NT * OUT_ROWS), gx0, xp, yp, vx, vy, Fx, Fy);

    const int tx = t & 31;
    const int ty = t >> 5;                    // 0..3
    const int xl = tx << 2;
    const int xb = xb0 + xl;
    const float xk0 = (float)xb;
    const float xdst[4] = {xk0, xk0 + 1.0f, xk0 + 2.0f, xk0 + 3.0f};
    const size_t P = (size_t)NXD * NXD;

    int cur = 0;
    #pragma unroll 1
    for (int it = 0; it < NT; ++it) {
        const int y0b = yg * (NT * OUT_ROWS) + it * OUT_ROWS;

        // prefetch next tile into the other buffer (freed by last iter's sync)
        if ((t == 0) && (it + 1 < NT))
            stage_tile(cur ? buf0 : buf1, cur ? mb0 : mb1,
                       y0b + OUT_ROWS, gx0, xp, yp, vx, vy, Fx, Fy);

        mbar_wait(cur ? mb1 : mb0, (uint32_t)((it >> 1) & 1));

        const float* B = cur ? buf1 : buf0;
        const int y0 = y0b + (ty << 1);
        const float fy0 = (float)y0;
        const float fy1 = (float)(y0 + 1);

        float aA[2][4] = {{0.f,0.f,0.f,0.f},{0.f,0.f,0.f,0.f}};
        float aU[2][4] = {{0.f,0.f,0.f,0.f},{0.f,0.f,0.f,0.f}};
        float aV[2][4] = {{0.f,0.f,0.f,0.f},{0.f,0.f,0.f,0.f}};
        float aX[2][4] = {{0.f,0.f,0.f,0.f},{0.f,0.f,0.f,0.f}};
        float aY[2][4] = {{0.f,0.f,0.f,0.f},{0.f,0.f,0.f,0.f}};

        #pragma unroll
        for (int r = 0; r < 4; ++r) {             // src rows y0-1 .. y0+2
            const int sr = (ty << 1) + r;
            const int dmin = (r == 3) ? 1 : 0;
            const int dmax = (r == 0) ? 0 : 1;

            float ny[2][6];
            float nx[12];
            {
                float4 qx = *reinterpret_cast<const float4*>(&SMF(B, 0, sr, 4 + xl));
                float xl0 = SMF(B, 0, sr, 3 + xl), xr0 = SMF(B, 0, sr, 8 + xl);
                float4 qy = *reinterpret_cast<const float4*>(&SMF(B, 1, sr, 4 + xl));
                float yl0 = SMF(B, 1, sr, 3 + xl), yr0 = SMF(B, 1, sr, 8 + xl);
                float xps[6] = {xl0, qx.x, qx.y, qx.z, qx.w, xr0};
                float yps[6] = {yl0, qy.x, qy.y, qy.z, qy.w, yr0};
                int idx = 0;
                #pragma unroll
                for (int s = 0; s < 6; ++s) {
                    #pragma unroll
                    for (int d = dmin; d <= dmax; ++d)
                        ny[d][s] = tent(yps[s] - (d ? fy1 : fy0));
                    #pragma unroll
                    for (int k = kmin_of(s); k <= kmax_of(s); ++k)
                        nx[idx++] = tent(xps[s] - xdst[k]);
                }
            }
            {
                float4 qu = *reinterpret_cast<const float4*>(&SMF(B, 2, sr, 4 + xl));
                float ul = SMF(B, 2, sr, 3 + xl), ur = SMF(B, 2, sr, 8 + xl);
                float4 qv = *reinterpret_cast<const float4*>(&SMF(B, 3, sr, 4 + xl));
                float vl = SMF(B, 3, sr, 3 + xl), vr = SMF(B, 3, sr, 8 + xl);
                float vxs[6] = {ul, qu.x, qu.y, qu.z, qu.w, ur};
                float vys[6] = {vl, qv.x, qv.y, qv.z, qv.w, vr};
                int idx = 0;
                #pragma unroll
                for (int s = 0; s < 6; ++s) {
                    const int i0 = idx;
                    #pragma unroll
                    for (int d = dmin; d <= dmax; ++d) {
                        float n  = ny[d][s];
                        float tu = n * vxs[s];
                        float tv = n * vys[s];
                        int ii = i0;
                        #pragma unroll
                        for (int k = kmin_of(s); k <= kmax_of(s); ++k, ++ii) {
                            float w = nx[ii];
                            aA[d][k] = fmaf(w, n,  aA[d][k]);
                            aU[d][k] = fmaf(w, tu, aU[d][k]);
                            aV[d][k] = fmaf(w, tv, aV[d][k]);
                        }
                    }
                    idx += kmax_of(s) - kmin_of(s) + 1;
                }
            }
            {
                float4 qa = *reinterpret_cast<const float4*>(&SMF(B, 4, sr, 4 + xl));
                float al = SMF(B, 4, sr, 3 + xl), ar = SMF(B, 4, sr, 8 + xl);
                float4 qb = *reinterpret_cast<const float4*>(&SMF(B, 5, sr, 4 + xl));
                float bl = SMF(B, 5, sr, 3 + xl), br = SMF(B, 5, sr, 8 + xl);
                float fxs[6] = {al, qa.x, qa.y, qa.z, qa.w, ar};
                float fys[6] = {bl, qb.x, qb.y, qb.z, qb.w, br};
                int idx = 0;
                #pragma unroll
                for (int s = 0; s < 6; ++s) {
                    const int i0 = idx;
                    #pragma unroll
                    for (int d = dmin; d <= dmax; ++d) {
                        float n   = ny[d][s];
                        float txv = n * fxs[s];
                        float tyv = n * fys[s];
                        int ii = i0;
                        #pragma unroll
                        for (int k = kmin_of(s); k <= kmax_of(s); ++k, ++ii) {
                            float w = nx[ii];
                            aX[d][k] = fmaf(w, txv, aX[d][k]);
                            aY[d][k] = fmaf(w, tyv, aY[d][k]);
                        }
                    }
                    idx += kmax_of(s) - kmin_of(s) + 1;
                }
            }
        }

        // mask (at destination) * VP, then store 5 planes
        #pragma unroll
        for (int d = 0; d < 2; ++d) {
            size_t o = ((size_t)(y0 + d) << 12) + xb;
            float4 mq = *reinterpret_cast<const float4*>(mk + o);
            float md[4] = {mq.x * VP, mq.y * VP, mq.z * VP, mq.w * VP};

            #pragma unroll
            for (int k = 0; k < 4; ++k) {
                aA[d][k] *= md[k]; aU[d][k] *= md[k]; aV[d][k] *= md[k];
                aX[d][k] *= md[k]; aY[d][k] *= md[k];
            }

            *reinterpret_cast<float4*>(out + o)         = make_float4(aA[d][0], aA[d][1], aA[d][2], aA[d][3]);
            *reinterpret_cast<float4*>(out + P + o)     = make_float4(aU[d][0], aU[d][1], aU[d][2], aU[d][3]);
            *reinterpret_cast<float4*>(out + 2 * P + o) = make_float4(aV[d][0], aV[d][1], aV[d][2], aV[d][3]);
            *reinterpret_cast<float4*>(out + 3 * P + o) = make_float4(aX[d][0], aX[d][1], aX[d][2], aX[d][3]);
            *reinterpret_cast<float4*>(out + 4 * P + o) = make_float4(aY[d][0], aY[d][1], aY[d][2], aY[d][3]);
        }

        __syncthreads();   // all done reading buf[cur]; next iter may re-arm it
        cur ^= 1;
    }
}

extern "C" void kernel_launch(void* const* d_in, const int* in_sizes, int n_in,
                              void* d_out, int out_size)
{
    const float* xp = (const float*)d_in[0];
    const float* yp = (const float*)d_in[1];
    // d_in[2] = x_grid, d_in[3] = y_grid: analytic (x, y), not needed.
    const float* vx = (const float*)d_in[4];
    const float* vy = (const float*)d_in[5];
    const float* Fx = (const float*)d_in[6];
    const float* Fy = (const float*)d_in[7];
    const float* mk = (const float*)d_in[8];
    float* out = (float*)d_out;

    const int smem_bytes = (8 + 2 * BUF_FLOATS) * (int)sizeof(float);  // 65,312
    cudaFuncSetAttribute(ai4dem_kernel,
                         cudaFuncAttributeMaxDynamicSharedMemorySize, smem_bytes);

    // 32 col-blocks x 128 y-groups; each block: 128 cols x 32 rows (4 tiles)
    ai4dem_kernel<<<32 * 128, BLK_T, smem_bytes>>>(xp, yp, vx, vy, Fx, Fy, mk, out);
}

// round 10
// speedup vs baseline: 1.5735x; 1.5735x over previous
#include <cuda_runtime.h>
#include <cstdint>

// AI4DEM coupling_backward: 3x3 tent-spline gather, 4096x4096 periodic grid.
// Inputs: xp, yp, x_grid(unused), y_grid(unused), vx, vy, Fx, Fy, mask
// Output: 5 planes [alpha, alpha_u, alpha_v, Fx, Fy], each 4096*4096 f32.
//
//   per tap: w = max(0,1-|xp_src - x_dst|) * max(0,1-|yp_src - y_dst|)
//   out     = mask_dst * VP * sum(w * field_src)     (mask at DESTINATION)
//
// R10: R7 structure (per-thread cp.async staging of a 10x136 tile, then
// compute a 2x4 output tile per thread) but with split commit groups and
// two-pass compute to hide the stage-wait bubble:
//   issue G1(xp,yp)+G2(vx,vy), G3(Fx,Fy)
//   wait<=1 -> pass A: weights + alpha/u/v; load mask; store planes 0-2
//              (G3 lands underneath)
//   wait 0  -> pass B: recompute weights + Fx/Fy; store planes 3-4
// Early stores also free the pass-A accumulators, keeping regs in the
// 6-blocks/SM budget (<=85).

#define NXD   4096
#define MASKW 4095

#define BLK_T    128
#define OUT_ROWS 8
#define SRC_ROWS 10
#define ROWW     136                     // 4 pad | 128 | 4 pad floats
#define ROWVECS  34
#define VECS_PER_FIELD (SRC_ROWS * ROWVECS)   // 340

__device__ __forceinline__ void cpa16(uint32_t saddr, const float* g) {
    asm volatile("cp.async.cg.shared.global [%0], [%1], 16;\n"
                 :: "r"(saddr), "l"(g));
}
__device__ __forceinline__ float tent(float d) {
    return fmaxf(1.0f - fabsf(d), 0.0f);
}
__device__ __forceinline__ constexpr int kmin_of(int s) { return (s - 2 > 0) ? (s - 2) : 0; }
__device__ __forceinline__ constexpr int kmax_of(int s) { return (s < 3) ? s : 3; }

// stage two fields into consecutive smem field-slots, then commit the group
__device__ __forceinline__ void stage2(float* s0, float* s1,
                                       const float* __restrict__ a,
                                       const float* __restrict__ b,
                                       int y0b, int xb0, int t)
{
    #pragma unroll 2
    for (int h = 0; h < 2; ++h) {
        const float* base = h ? b : a;
        float* sbase = h ? s1 : s0;
        for (int j = t; j < VECS_PER_FIELD; j += BLK_T) {
            int rr = j / ROWVECS;
            int v  = j - rr * ROWVECS;
            int gy = (y0b - 1 + rr) & MASKW;
            int gx = (xb0 - 4 + (v << 2)) & MASKW;
            uint32_t sa = (uint32_t)__cvta_generic_to_shared(sbase + rr * ROWW + (v << 2));
            cpa16(sa, base + ((size_t)gy << 12) + gx);
        }
    }
    asm volatile("cp.async.commit_group;\n" ::: "memory");
}

__global__ void __launch_bounds__(BLK_T, 6)
ai4dem_kernel(const float* __restrict__ xp, const float* __restrict__ yp,
              const float* __restrict__ vx, const float* __restrict__ vy,
              const float* __restrict__ Fx, const float* __restrict__ Fy,
              const float* __restrict__ mk, float* __restrict__ out)
{
    const float VP = 3.1415f / 6.0f;

    __shared__ float sm[6][SRC_ROWS][ROWW];   // 32,640 B

    const int t   = threadIdx.x;
    const int bx  = blockIdx.x & 31;
    const int by  = blockIdx.x >> 5;
    const int xb0 = bx << 7;
    const int y0b = by << 3;

    // ---- staging: 3 groups ----
    stage2(&sm[0][0][0], &sm[1][0][0], xp, yp, y0b, xb0, t);  // G1: coords
    stage2(&sm[2][0][0], &sm[3][0][0], vx, vy, y0b, xb0, t);  // G2
    stage2(&sm[4][0][0], &sm[5][0][0], Fx, Fy, y0b, xb0, t);  // G3

    const int tx = t & 31;
    const int ty = t >> 5;
    const int xl = tx << 2;
    const int xb = xb0 + xl;
    const int y0 = y0b + (ty << 1);
    const float fy0 = (float)y0;
    const float fy1 = (float)(y0 + 1);
    const float xk0 = (float)xb;
    const float xdst[4] = {xk0, xk0 + 1.0f, xk0 + 2.0f, xk0 + 3.0f};
    const size_t P = (size_t)NXD * NXD;

    // ---- wait for G1+G2 (G3 still in flight) ----
    asm volatile("cp.async.wait_group 1;\n" ::: "memory");
    __syncthreads();

    // ---- pass A: weights + alpha / u / v ----
    float aA[2][4] = {{0.f,0.f,0.f,0.f},{0.f,0.f,0.f,0.f}};
    float aU[2][4] = {{0.f,0.f,0.f,0.f},{0.f,0.f,0.f,0.f}};
    float aV[2][4] = {{0.f,0.f,0.f,0.f},{0.f,0.f,0.f,0.f}};

    #pragma unroll
    for (int r = 0; r < 4; ++r) {
        const int sr = (ty << 1) + r;
        const int dmin = (r == 3) ? 1 : 0;
        const int dmax = (r == 0) ? 0 : 1;

        float ny[2][6];
        float nx[12];
        {
            float4 qx = *reinterpret_cast<const float4*>(&sm[0][sr][4 + xl]);
            float xl0 = sm[0][sr][3 + xl], xr0 = sm[0][sr][8 + xl];
            float4 qy = *reinterpret_cast<const float4*>(&sm[1][sr][4 + xl]);
            float yl0 = sm[1][sr][3 + xl], yr0 = sm[1][sr][8 + xl];
            float xps[6] = {xl0, qx.x, qx.y, qx.z, qx.w, xr0};
            float yps[6] = {yl0, qy.x, qy.y, qy.z, qy.w, yr0};
            int idx = 0;
            #pragma unroll
            for (int s = 0; s < 6; ++s) {
                #pragma unroll
                for (int d = dmin; d <= dmax; ++d)
                    ny[d][s] = tent(yps[s] - (d ? fy1 : fy0));
                #pragma unroll
                for (int k = kmin_of(s); k <= kmax_of(s); ++k)
                    nx[idx++] = tent(xps[s] - xdst[k]);
            }
        }
        {
            float4 qu = *reinterpret_cast<const float4*>(&sm[2][sr][4 + xl]);
            float ul = sm[2][sr][3 + xl], ur = sm[2][sr][8 + xl];
            float4 qv = *reinterpret_cast<const float4*>(&sm[3][sr][4 + xl]);
            float vl = sm[3][sr][3 + xl], vr = sm[3][sr][8 + xl];
            float vxs[6] = {ul, qu.x, qu.y, qu.z, qu.w, ur};
            float vys[6] = {vl, qv.x, qv.y, qv.z, qv.w, vr};
            int idx = 0;
            #pragma unroll
            for (int s = 0; s < 6; ++s) {
                const int i0 = idx;
                #pragma unroll
                for (int d = dmin; d <= dmax; ++d) {
                    float n  = ny[d][s];
                    float tu = n * vxs[s];
                    float tv = n * vys[s];
                    int ii = i0;
                    #pragma unroll
                    for (int k = kmin_of(s); k <= kmax_of(s); ++k, ++ii) {
                        float w = nx[ii];
                        aA[d][k] = fmaf(w, n,  aA[d][k]);
                        aU[d][k] = fmaf(w, tu, aU[d][k]);
                        aV[d][k] = fmaf(w, tv, aV[d][k]);
                    }
                }
                idx += kmax_of(s) - kmin_of(s) + 1;
            }
        }
    }

    // ---- mask, scale, store planes 0-2 (overlaps G3 in flight) ----
    float md0[4], md1[4];
    {
        size_t o0 = ((size_t)y0 << 12) + xb;
        size_t o1 = o0 + NXD;
        float4 m0 = *reinterpret_cast<const float4*>(mk + o0);
        float4 m1 = *reinterpret_cast<const float4*>(mk + o1);
        md0[0] = m0.x * VP; md0[1] = m0.y * VP; md0[2] = m0.z * VP; md0[3] = m0.w * VP;
        md1[0] = m1.x * VP; md1[1] = m1.y * VP; md1[2] = m1.z * VP; md1[3] = m1.w * VP;

        #pragma unroll
        for (int k = 0; k < 4; ++k) {
            aA[0][k] *= md0[k]; aU[0][k] *= md0[k]; aV[0][k] *= md0[k];
            aA[1][k] *= md1[k]; aU[1][k] *= md1[k]; aV[1][k] *= md1[k];
        }
        *reinterpret_cast<float4*>(out + o0)         = make_float4(aA[0][0], aA[0][1], aA[0][2], aA[0][3]);
        *reinterpret_cast<float4*>(out + o1)         = make_float4(aA[1][0], aA[1][1], aA[1][2], aA[1][3]);
        *reinterpret_cast<float4*>(out + P + o0)     = make_float4(aU[0][0], aU[0][1], aU[0][2], aU[0][3]);
        *reinterpret_cast<float4*>(out + P + o1)     = make_float4(aU[1][0], aU[1][1], aU[1][2], aU[1][3]);
        *reinterpret_cast<float4*>(out + 2 * P + o0) = make_float4(aV[0][0], aV[0][1], aV[0][2], aV[0][3]);
        *reinterpret_cast<float4*>(out + 2 * P + o1) = make_float4(aV[1][0], aV[1][1], aV[1][2], aV[1][3]);
    }

    // ---- wait for G3, then pass B: recompute weights + Fx / Fy ----
    asm volatile("cp.async.wait_group 0;\n" ::: "memory");
    __syncthreads();

    float aX[2][4] = {{0.f,0.f,0.f,0.f},{0.f,0.f,0.f,0.f}};
    float aY[2][4] = {{0.f,0.f,0.f,0.f},{0.f,0.f,0.f,0.f}};

    #pragma unroll
    for (int r = 0; r < 4; ++r) {
        const int sr = (ty << 1) + r;
        const int dmin = (r == 3) ? 1 : 0;
        const int dmax = (r == 0) ? 0 : 1;

        float ny[2][6];
        float nx[12];
        {
            float4 qx = *reinterpret_cast<const float4*>(&sm[0][sr][4 + xl]);
            float xl0 = sm[0][sr][3 + xl], xr0 = sm[0][sr][8 + xl];
            float4 qy = *reinterpret_cast<const float4*>(&sm[1][sr][4 + xl]);
            float yl0 = sm[1][sr][3 + xl], yr0 = sm[1][sr][8 + xl];
            float xps[6] = {xl0, qx.x, qx.y, qx.z, qx.w, xr0};
            float yps[6] = {yl0, qy.x, qy.y, qy.z, qy.w, yr0};
            int idx = 0;
            #pragma unroll
            for (int s = 0; s < 6; ++s) {
                #pragma unroll
                for (int d = dmin; d <= dmax; ++d)
                    ny[d][s] = tent(yps[s] - (d ? fy1 : fy0));
                #pragma unroll
                for (int k = kmin_of(s); k <= kmax_of(s); ++k)
                    nx[idx++] = tent(xps[s] - xdst[k]);
            }
        }
        {
            float4 qa = *reinterpret_cast<const float4*>(&sm[4][sr][4 + xl]);
            float al = sm[4][sr][3 + xl], ar = sm[4][sr][8 + xl];
            float4 qb = *reinterpret_cast<const float4*>(&sm[5][sr][4 + xl]);
            float bl = sm[5][sr][3 + xl], br = sm[5][sr][8 + xl];
            float fxs[6] = {al, qa.x, qa.y, qa.z, qa.w, ar};
            float fys[6] = {bl, qb.x, qb.y, qb.z, qb.w, br};
            int idx = 0;
            #pragma unroll
            for (int s = 0; s < 6; ++s) {
                const int i0 = idx;
                #pragma unroll
                for (int d = dmin; d <= dmax; ++d) {
                    float n   = ny[d][s];
                    float txv = n * fxs[s];
                    float tyv = n * fys[s];
                    int ii = i0;
                    #pragma unroll
                    for (int k = kmin_of(s); k <= kmax_of(s); ++k, ++ii) {
                        float w = nx[ii];
                        aX[d][k] = fmaf(w, txv, aX[d][k]);
                        aY[d][k] = fmaf(w, tyv, aY[d][k]);
                    }
                }
                idx += kmax_of(s) - kmin_of(s) + 1;
            }
        }
    }

    {
        size_t o0 = ((size_t)y0 << 12) + xb;
        size_t o1 = o0 + NXD;
        #pragma unroll
        for (int k = 0; k < 4; ++k) {
            aX[0][k] *= md0[k]; aY[0][k] *= md0[k];
            aX[1][k] *= md1[k]; aY[1][k] *= md1[k];
        }
        *reinterpret_cast<float4*>(out + 3 * P + o0) = make_float4(aX[0][0], aX[0][1], aX[0][2], aX[0][3]);
        *reinterpret_cast<float4*>(out + 3 * P + o1) = make_float4(aX[1][0], aX[1][1], aX[1][2], aX[1][3]);
        *reinterpret_cast<float4*>(out + 4 * P + o0) = make_float4(aY[0][0], aY[0][1], aY[0][2], aY[0][3]);
        *reinterpret_cast<float4*>(out + 4 * P + o1) = make_float4(aY[1][0], aY[1][1], aY[1][2], aY[1][3]);
    }
}

extern "C" void kernel_launch(void* const* d_in, const int* in_sizes, int n_in,
                              void* d_out, int out_size)
{
    const float* xp = (const float*)d_in[0];
    const float* yp = (const float*)d_in[1];
    // d_in[2] = x_grid, d_in[3] = y_grid: analytic (x, y), not needed.
    const float* vx = (const float*)d_in[4];
    const float* vy = (const float*)d_in[5];
    const float* Fx = (const float*)d_in[6];
    const float* Fy = (const float*)d_in[7];
    const float* mk = (const float*)d_in[8];
    float* out = (float*)d_out;

    // 32 col-blocks x 512 row-blocks; each block: 128 cols x 8 rows of output
    ai4dem_kernel<<<32 * 512, BLK_T>>>(xp, yp, vx, vy, Fx, Fy, mk, out);
}

// round 11
// speedup vs baseline: 1.8675x; 1.1869x over previous
#include <cuda_runtime.h>
#include <cstdint>

// AI4DEM coupling_backward: 3x3 tent-spline gather, 4096x4096 periodic grid.
// Inputs: xp, yp, x_grid(unused), y_grid(unused), vx, vy, Fx, Fy, mask
// Output: 5 planes [alpha, alpha_u, alpha_v, Fx, Fy], each 4096*4096 f32.
//
//   per tap: w = max(0,1-|xp_src - x_dst|) * max(0,1-|yp_src - y_dst|)
//   out     = mask_dst * VP * sum(w * field_src)     (mask at DESTINATION)
//
// R11 = R7 (cp.async staging of a 10x136x6 tile, one barrier, 2x4 outputs
// per thread) + mask staged through smem as a 7th plane (8x128, no halo).
// R7's only synchronous global load was the mask float4 pair at the END of
// the block: a full DRAM latency with nothing to overlap it. Staged in the
// same commit group, that latency hides under the existing wait.
// smem 36.7KB and regs ~80 both still give 6 blocks/SM.

#define NXD   4096
#define MASKW 4095

#define BLK_T    128          // threads per block
#define OUT_ROWS 8            // output rows per block
#define SRC_ROWS 10           // OUT_ROWS + 2 halo rows
#define ROWW     136          // 4 pad | 128 main | 4 pad  (floats)
#define ROWVECS  34           // ROWW / 4 float4s per field-row
#define VECS_PER_FIELD (SRC_ROWS * ROWVECS)   // 340
#define MK_VECS  (OUT_ROWS * 32)              // 256 float4s of mask

__device__ __forceinline__ void cpa16(uint32_t saddr, const float* g) {
    asm volatile("cp.async.cg.shared.global [%0], [%1], 16;\n"
                 :: "r"(saddr), "l"(g));
}

__device__ __forceinline__ float tent(float d) {
    return fmaxf(1.0f - fabsf(d), 0.0f);
}

__device__ __forceinline__ constexpr int kmin_of(int s) { return (s - 2 > 0) ? (s - 2) : 0; }
__device__ __forceinline__ constexpr int kmax_of(int s) { return (s < 3) ? s : 3; }

__global__ void __launch_bounds__(BLK_T, 6)
ai4dem_kernel(const float* __restrict__ xp, const float* __restrict__ yp,
              const float* __restrict__ vx, const float* __restrict__ vy,
              const float* __restrict__ Fx, const float* __restrict__ Fy,
              const float* __restrict__ mk, float* __restrict__ out)
{
    const float VP = 3.1415f / 6.0f;

    __shared__ float sm[6][SRC_ROWS][ROWW];   // 32,640 B
    __shared__ float smk[OUT_ROWS][128];      //  4,096 B

    const int t   = threadIdx.x;
    const int bx  = blockIdx.x & 31;          // 32 col-blocks
    const int by  = blockIdx.x >> 5;          // 512 row-blocks
    const int xb0 = bx << 7;                  // block's first col
    const int y0b = by << 3;                  // block's first out row

    // ---- stage 6 fields x 10 rows x 136 cols + mask 8x128 via cp.async ----
    {
        const float* fptr[6] = {xp, yp, vx, vy, Fx, Fy};
        #pragma unroll
        for (int f = 0; f < 6; ++f) {
            const float* base = fptr[f];
            #pragma unroll
            for (int j = t; j < VECS_PER_FIELD; j += BLK_T) {
                int rr = j / ROWVECS;                 // 0..9
                int v  = j - rr * ROWVECS;            // 0..33
                int gy = (y0b - 1 + rr) & MASKW;
                int gx = (xb0 - 4 + (v << 2)) & MASKW;   // 16B-aligned, wraps whole
                uint32_t sa = (uint32_t)__cvta_generic_to_shared(&sm[f][rr][v << 2]);
                cpa16(sa, base + ((size_t)gy << 12) + gx);
            }
        }
        // mask: 8 rows x 128 cols, aligned, no halo (y0b+7 <= 4095 always)
        #pragma unroll
        for (int j = t; j < MK_VECS; j += BLK_T) {
            int rr = j >> 5;                          // 0..7
            int v  = j & 31;                          // 0..31
            uint32_t sa = (uint32_t)__cvta_generic_to_shared(&smk[rr][v << 2]);
            cpa16(sa, mk + ((size_t)(y0b + rr) << 12) + xb0 + (v << 2));
        }
        asm volatile("cp.async.commit_group;\n" ::: "memory");
        asm volatile("cp.async.wait_group 0;\n" ::: "memory");
        __syncthreads();
    }

    // ---- compute: each thread a 2x4 output tile ----
    const int tx = t & 31;                    // col quad within block
    const int ty = t >> 5;                    // row pair within block (0..3)
    const int xl = tx << 2;                   // local col offset
    const int xb = xb0 + xl;                  // global base col
    const int y0 = y0b + (ty << 1);           // global first out row

    const float fy0 = (float)y0;
    const float fy1 = (float)(y0 + 1);
    const float xk0 = (float)xb;
    const float xdst[4] = {xk0, xk0 + 1.0f, xk0 + 2.0f, xk0 + 3.0f};

    float aA[2][4] = {{0.f,0.f,0.f,0.f},{0.f,0.f,0.f,0.f}};
    float aU[2][4] = {{0.f,0.f,0.f,0.f},{0.f,0.f,0.f,0.f}};
    float aV[2][4] = {{0.f,0.f,0.f,0.f},{0.f,0.f,0.f,0.f}};
    float aX[2][4] = {{0.f,0.f,0.f,0.f},{0.f,0.f,0.f,0.f}};
    float aY[2][4] = {{0.f,0.f,0.f,0.f},{0.f,0.f,0.f,0.f}};

    #pragma unroll
    for (int r = 0; r < 4; ++r) {             // src rows y0-1 .. y0+2
        const int sr = (ty << 1) + r;         // smem row 0..9

        // tent support: src row r reaches dst rows within distance 1
        const int dmin = (r == 3) ? 1 : 0;
        const int dmax = (r == 0) ? 0 : 1;

        // coords -> weights (xp/yp regs die immediately)
        float ny[2][6];
        float nx[12];
        {
            float4 qx = *reinterpret_cast<const float4*>(&sm[0][sr][4 + xl]);
            float xl0 = sm[0][sr][3 + xl], xr0 = sm[0][sr][8 + xl];
            float4 qy = *reinterpret_cast<const float4*>(&sm[1][sr][4 + xl]);
            float yl0 = sm[1][sr][3 + xl], yr0 = sm[1][sr][8 + xl];
            float xps[6] = {xl0, qx.x, qx.y, qx.z, qx.w, xr0};
            float yps[6] = {yl0, qy.x, qy.y, qy.z, qy.w, yr0};
            int idx = 0;
            #pragma unroll
            for (int s = 0; s < 6; ++s) {
                #pragma unroll
                for (int d = dmin; d <= dmax; ++d)
                    ny[d][s] = tent(yps[s] - (d ? fy1 : fy0));
                #pragma unroll
                for (int k = kmin_of(s); k <= kmax_of(s); ++k)
                    nx[idx++] = tent(xps[s] - xdst[k]);
            }
        }

        // vx / vy + alpha
        {
            float4 qu = *reinterpret_cast<const float4*>(&sm[2][sr][4 + xl]);
            float ul = sm[2][sr][3 + xl], ur = sm[2][sr][8 + xl];
            float4 qv = *reinterpret_cast<const float4*>(&sm[3][sr][4 + xl]);
            float vl = sm[3][sr][3 + xl], vr = sm[3][sr][8 + xl];
            float vxs[6] = {ul, qu.x, qu.y, qu.z, qu.w, ur};
            float vys[6] = {vl, qv.x, qv.y, qv.z, qv.w, vr};
            int idx = 0;
            #pragma unroll
            for (int s = 0; s < 6; ++s) {
                const int i0 = idx;
                #pragma unroll
                for (int d = dmin; d <= dmax; ++d) {
                    float n  = ny[d][s];
                    float tu = n * vxs[s];
                    float tv = n * vys[s];
                    int ii = i0;
                    #pragma unroll
                    for (int k = kmin_of(s); k <= kmax_of(s); ++k, ++ii) {
                        float w = nx[ii];
                        aA[d][k] = fmaf(w, n,  aA[d][k]);
                        aU[d][k] = fmaf(w, tu, aU[d][k]);
                        aV[d][k] = fmaf(w, tv, aV[d][k]);
                    }
                }
                idx += kmax_of(s) - kmin_of(s) + 1;
            }
        }

        // Fx / Fy
        {
            float4 qa = *reinterpret_cast<const float4*>(&sm[4][sr][4 + xl]);
            float al = sm[4][sr][3 + xl], ar = sm[4][sr][8 + xl];
            float4 qb = *reinterpret_cast<const float4*>(&sm[5][sr][4 + xl]);
            float bl = sm[5][sr][3 + xl], br = sm[5][sr][8 + xl];
            float fxs[6] = {al, qa.x, qa.y, qa.z, qa.w, ar};
            float fys[6] = {bl, qb.x, qb.y, qb.z, qb.w, br};
            int idx = 0;
            #pragma unroll
            for (int s = 0; s < 6; ++s) {
                const int i0 = idx;
                #pragma unroll
                for (int d = dmin; d <= dmax; ++d) {
                    float n   = ny[d][s];
                    float txv = n * fxs[s];
                    float tyv = n * fys[s];
                    int ii = i0;
                    #pragma unroll
                    for (int k = kmin_of(s); k <= kmax_of(s); ++k, ++ii) {
                        float w = nx[ii];
                        aX[d][k] = fmaf(w, txv, aX[d][k]);
                        aY[d][k] = fmaf(w, tyv, aY[d][k]);
                    }
                }
                idx += kmax_of(s) - kmin_of(s) + 1;
            }
        }
    }

    // ---- mask (from smem, staged) * VP, then store 5 planes ----
    const size_t P = (size_t)NXD * NXD;
    #pragma unroll
    for (int d = 0; d < 2; ++d) {
        size_t o = ((size_t)(y0 + d) << 12) + xb;
        float4 mq = *reinterpret_cast<const float4*>(&smk[(ty << 1) + d][xl]);
        float md[4] = {mq.x * VP, mq.y * VP, mq.z * VP, mq.w * VP};

        #pragma unroll
        for (int k = 0; k < 4; ++k) {
            aA[d][k] *= md[k]; aU[d][k] *= md[k]; aV[d][k] *= md[k];
            aX[d][k] *= md[k]; aY[d][k] *= md[k];
        }

        *reinterpret_cast<float4*>(out + o)         = make_float4(aA[d][0], aA[d][1], aA[d][2], aA[d][3]);
        *reinterpret_cast<float4*>(out + P + o)     = make_float4(aU[d][0], aU[d][1], aU[d][2], aU[d][3]);
        *reinterpret_cast<float4*>(out + 2 * P + o) = make_float4(aV[d][0], aV[d][1], aV[d][2], aV[d][3]);
        *reinterpret_cast<float4*>(out + 3 * P + o) = make_float4(aX[d][0], aX[d][1], aX[d][2], aX[d][3]);
        *reinterpret_cast<float4*>(out + 4 * P + o) = make_float4(aY[d][0], aY[d][1], aY[d][2], aY[d][3]);
    }
}

extern "C" void kernel_launch(void* const* d_in, const int* in_sizes, int n_in,
                              void* d_out, int out_size)
{
    const float* xp = (const float*)d_in[0];
    const float* yp = (const float*)d_in[1];
    // d_in[2] = x_grid, d_in[3] = y_grid: analytic (x, y), not needed.
    const float* vx = (const float*)d_in[4];
    const float* vy = (const float*)d_in[5];
    const float* Fx = (const float*)d_in[6];
    const float* Fy = (const float*)d_in[7];
    const float* mk = (const float*)d_in[8];
    float* out = (float*)d_out;

    // 32 col-blocks x 512 row-blocks; each block: 128 cols x 8 rows of output
    ai4dem_kernel<<<32 * 512, BLK_T>>>(xp, yp, vx, vy, Fx, Fy, mk, out);
}